// round 14
// baseline (speedup 1.0000x reference)
#include <cuda_runtime.h>
#include <cuda_bf16.h>
#include <math.h>
#include <cstdint>

// Problem constants
#define NMAX   50000
#define EMAX   800000
#define HEADS  4
#define HID    64
#define QK     256        // HEADS*HID
#define OCT    832        // 3*QK + HID
#define NGRAPH 64
#define GDIM   256
#define NCLS   10

// ---------------- scratch (device globals; no runtime allocation) ----------------
__device__ __align__(16) __nv_bfloat16 g_qb[NMAX * QK];   // bf16 q
__device__ __align__(16) __nv_bfloat16 g_kb[NMAX * QK];   // bf16 k
__device__ __align__(16) __nv_bfloat16 g_vb[NMAX * QK];   // bf16 v
__device__ __align__(16) float    g_skip[NMAX * HID];
__device__ __align__(16) __nv_bfloat16 g_h1b[NMAX * HID]; // conv1 out (bf16 = GEMM2's A)
__device__ __align__(16) float    g_h2  [NMAX * HID];
__device__ __align__(16) float    g_Wc  [128 * OCT];
__device__ __align__(16) float    g_bc  [OCT];
__device__ __align__(16) float    g_gsum[NGRAPH * HID];
__device__ __align__(16) float    g_gcnt[NGRAPH];
// CSR (dst-sorted) graph, built once per launch
__device__ __align__(16) int      g_rowptr[NMAX + 1];
__device__ __align__(16) int      g_cursor[NMAX];
__device__ __align__(16) int      g_srcs  [EMAX];

// ---------------- helpers ----------------
__device__ __forceinline__ uint32_t pack_bf16(float a, float b) {
    __nv_bfloat16 ha = __float2bfloat16_rn(a);
    __nv_bfloat16 hb = __float2bfloat16_rn(b);
    return (uint32_t)__bfloat16_as_ushort(ha) | ((uint32_t)__bfloat16_as_ushort(hb) << 16);
}
__device__ __forceinline__ float bf_hi_res(float v) {   // v - bf16(v)
    return v - __bfloat162float(__float2bfloat16_rn(v));
}
__device__ __forceinline__ float bflo(uint32_t u) { return __uint_as_float(u << 16); }
__device__ __forceinline__ float bfhi(uint32_t u) { return __uint_as_float(u & 0xffff0000u); }
__device__ __forceinline__ float dot2bf(uint32_t ua, uint32_t ub) {
    return bflo(ua) * bflo(ub) + bfhi(ua) * bfhi(ub);
}

#define MMA_BF16(c, a, b)                                                     \
    asm volatile("mma.sync.aligned.m16n8k16.row.col.f32.bf16.bf16.f32 "       \
                 "{%0,%1,%2,%3}, {%4,%5,%6,%7}, {%8,%9}, {%0,%1,%2,%3};"      \
                 : "+f"((c)[0]), "+f"((c)[1]), "+f"((c)[2]), "+f"((c)[3])     \
                 : "r"((a)[0]), "r"((a)[1]), "r"((a)[2]), "r"((a)[3]),        \
                   "r"((b)[0]), "r"((b)[1]))

// ---------------- CSR build ----------------
__global__ void hist_kernel(const int* __restrict__ ei, int E) {
    int e = blockIdx.x * blockDim.x + threadIdx.x;
    if (e < E) atomicAdd(&g_cursor[ei[E + e]], 1);
}
__global__ void scan_kernel(int N, int E) {
    __shared__ int s_part[1024];
    int t = threadIdx.x;
    int chunk = (N + 1023) >> 10;
    int b = t * chunk, en = min(b + chunk, N);
    int sum = 0;
    for (int i = b; i < en; i++) sum += g_cursor[i];
    s_part[t] = sum;
    __syncthreads();
    for (int off = 1; off < 1024; off <<= 1) {
        int v = (t >= off) ? s_part[t - off] : 0;
        __syncthreads();
        s_part[t] += v;
        __syncthreads();
    }
    int run = s_part[t] - sum;   // exclusive base
    for (int i = b; i < en; i++) {
        int c = g_cursor[i];
        g_rowptr[i] = run;
        g_cursor[i] = run;
        run += c;
    }
    if (t == 0) g_rowptr[N] = E;
}
__global__ void scatter_kernel(const int* __restrict__ ei, int E) {
    int e = blockIdx.x * blockDim.x + threadIdx.x;
    if (e >= E) return;
    int src = ei[e], dst = ei[E + e];
    int pos = atomicAdd(&g_cursor[dst], 1);
    g_srcs[pos] = src;
}

// ---------------- weight pack ----------------
__global__ void pack_w(const float* __restrict__ Wq, const float* __restrict__ bq,
                       const float* __restrict__ Wk, const float* __restrict__ bk,
                       const float* __restrict__ Wv, const float* __restrict__ bv,
                       const float* __restrict__ Ws, const float* __restrict__ bs, int K) {
    int idx = blockIdx.x * blockDim.x + threadIdx.x;
    int tot = K * OCT;
    if (idx < tot) {
        int k = idx / OCT, j = idx - k * OCT;
        float v;
        if      (j < 256) v = Wq[k * 256 + j];
        else if (j < 512) v = Wk[k * 256 + (j - 256)];
        else if (j < 768) v = Wv[k * 256 + (j - 512)];
        else              v = Ws[k * 64  + (j - 768)];
        g_Wc[idx] = v;
    }
    if (idx < OCT) {
        float b;
        if      (idx < 256) b = bq[idx];
        else if (idx < 512) b = bk[idx - 256];
        else if (idx < 768) b = bv[idx - 512];
        else                b = bs[idx - 768];
        g_bc[idx] = b;
    }
}

// ---------------- GEMM: 2-term bf16 mma.sync.m16n8k16 (A bf16, B hi/lo split) --------
#define ASTR32 136
#define BSTR32 72
template<int IN_BF>
__global__ void __launch_bounds__(256, 2) gemm_qkvs(const void* __restrict__ Ap, int N, int K) {
    __shared__ uint32_t As[8 * ASTR32];      // [kpair][m]
    __shared__ uint32_t Bs[2][8 * BSTR32];   // [hi/lo][kpair][n]
    const int t    = threadIdx.x;
    const int lane = t & 31, wid = t >> 5;
    const int warp_m = wid & 3;
    const int warp_n = wid >> 2;
    const int row0 = blockIdx.x * 128, col0 = blockIdx.y * 64;
    const int lq = lane >> 2;
    const int lr = lane & 3;

    float c[2][4][4];
    #pragma unroll
    for (int mt = 0; mt < 2; mt++)
        #pragma unroll
        for (int nt = 0; nt < 4; nt++)
            #pragma unroll
            for (int i = 0; i < 4; i++) c[mt][nt][i] = 0.f;

    for (int k0 = 0; k0 < K; k0 += 16) {
        if (IN_BF) {
            const __nv_bfloat16* A = (const __nv_bfloat16*)Ap;
            int r = t >> 1, half = t & 1;
            int gr = row0 + r;
            uint4 a = (gr < N) ? *(const uint4*)&A[(size_t)gr * K + k0 + half * 8]
                               : make_uint4(0u, 0u, 0u, 0u);
            int kp = half * 4;
            As[(kp + 0) * ASTR32 + r] = a.x;
            As[(kp + 1) * ASTR32 + r] = a.y;
            As[(kp + 2) * ASTR32 + r] = a.z;
            As[(kp + 3) * ASTR32 + r] = a.w;
        } else {
            const float* A = (const float*)Ap;
            #pragma unroll
            for (int ii = 0; ii < 2; ii++) {
                int idx = t + ii * 256;
                int r = idx >> 2, cg = (idx & 3) << 2;
                int gr = row0 + r;
                float4 a = (gr < N) ? *(const float4*)&A[(size_t)gr * K + k0 + cg]
                                    : make_float4(0.f, 0.f, 0.f, 0.f);
                int kp = cg >> 1;
                As[kp * ASTR32 + r]       = pack_bf16(a.x, a.y);
                As[(kp + 1) * ASTR32 + r] = pack_bf16(a.z, a.w);
            }
        }
        if (t < 128) {
            int kp = t >> 4, j4 = (t & 15) << 2;
            const float* r0p = &g_Wc[(size_t)(k0 + 2 * kp) * OCT + col0 + j4];
            const float* r1p = r0p + OCT;
            float4 b0 = *(const float4*)r0p;
            float4 b1 = *(const float4*)r1p;
            float v0[4] = {b0.x, b0.y, b0.z, b0.w};
            float v1[4] = {b1.x, b1.y, b1.z, b1.w};
            #pragma unroll
            for (int i = 0; i < 4; i++) {
                Bs[0][kp * BSTR32 + j4 + i] = pack_bf16(v0[i], v1[i]);
                Bs[1][kp * BSTR32 + j4 + i] = pack_bf16(bf_hi_res(v0[i]), bf_hi_res(v1[i]));
            }
        }
        __syncthreads();

        uint32_t ah[2][4];
        #pragma unroll
        for (int mt = 0; mt < 2; mt++) {
            int r0 = warp_m * 32 + mt * 16 + lq;
            ah[mt][0] = As[lr * ASTR32 + r0];
            ah[mt][1] = As[lr * ASTR32 + r0 + 8];
            ah[mt][2] = As[(lr + 4) * ASTR32 + r0];
            ah[mt][3] = As[(lr + 4) * ASTR32 + r0 + 8];
        }
        uint32_t bh[4][2], bl[4][2];
        #pragma unroll
        for (int nt = 0; nt < 4; nt++) {
            int n = warp_n * 32 + nt * 8 + lq;
            bh[nt][0] = Bs[0][lr * BSTR32 + n];
            bh[nt][1] = Bs[0][(lr + 4) * BSTR32 + n];
            bl[nt][0] = Bs[1][lr * BSTR32 + n];
            bl[nt][1] = Bs[1][(lr + 4) * BSTR32 + n];
        }
        #pragma unroll
        for (int mt = 0; mt < 2; mt++)
            #pragma unroll
            for (int nt = 0; nt < 4; nt++) {
                MMA_BF16(c[mt][nt], ah[mt], bh[nt]);
                MMA_BF16(c[mt][nt], ah[mt], bl[nt]);
            }
        __syncthreads();
    }

    int y = blockIdx.y;
    bool is_bf = (y < 12);
    __nv_bfloat16* bfdst; int bfoff;
    if      (y < 4) { bfdst = g_qb; bfoff = col0;       }
    else if (y < 8) { bfdst = g_kb; bfoff = col0 - 256; }
    else            { bfdst = g_vb; bfoff = col0 - 512; }

    #pragma unroll
    for (int mt = 0; mt < 2; mt++) {
        int r = row0 + warp_m * 32 + mt * 16 + lq;
        #pragma unroll
        for (int nt = 0; nt < 4; nt++) {
            int jc_in = warp_n * 32 + nt * 8 + lr * 2;
            float b0 = g_bc[col0 + jc_in];
            float b1 = g_bc[col0 + jc_in + 1];
            if (is_bf) {
                if (r < N) {
                    *(uint32_t*)&bfdst[(size_t)r * 256 + bfoff + jc_in] =
                        pack_bf16(c[mt][nt][0] + b0, c[mt][nt][1] + b1);
                }
                if (r + 8 < N) {
                    *(uint32_t*)&bfdst[(size_t)(r + 8) * 256 + bfoff + jc_in] =
                        pack_bf16(c[mt][nt][2] + b0, c[mt][nt][3] + b1);
                }
            } else {
                if (r < N) {
                    float2 o = make_float2(c[mt][nt][0] + b0, c[mt][nt][1] + b1);
                    *(float2*)&g_skip[(size_t)r * 64 + jc_in] = o;
                }
                if (r + 8 < N) {
                    float2 o = make_float2(c[mt][nt][2] + b0, c[mt][nt][3] + b1);
                    *(float2*)&g_skip[(size_t)(r + 8) * 64 + jc_in] = o;
                }
            }
        }
    }
}

// ---------------- fused edge conv: TWO warps per dst node (split edge list) ----------
// Each warp runs the 2-edge-unrolled chain on half the edges; partials combined in smem.
// Block = 256 threads = 8 warps = 4 nodes.
template<int OUT_BF>
__global__ void __launch_bounds__(256, 4) fused_edge(void* __restrict__ outp, int N) {
    __shared__ float s_acc[4][32][8];   // partner warp's partial acc
    __shared__ float s_z[4][32];        // partner warp's partial z
    int wid  = threadIdx.x >> 5;
    int lane = threadIdx.x & 31;
    int nl   = wid >> 1;                // local node 0..3
    int half = wid & 1;
    int node = blockIdx.x * 4 + nl;
    bool active = (node < N);

    float z = 0.f;
    float acc[8] = {0.f, 0.f, 0.f, 0.f, 0.f, 0.f, 0.f, 0.f};
    uint4 q = make_uint4(0u, 0u, 0u, 0u);
    int beg = 0, end = 0;

    if (active) {
        q = ((const uint4*)&g_qb[(size_t)node * QK])[lane];
        beg = g_rowptr[node];
        end = g_rowptr[node + 1];
        int deg = end - beg;
        int mid = beg + ((deg + 1) >> 1);
        int b = half ? mid : beg;
        int e = half ? end : mid;

        int i = b;
        for (; i + 2 <= e; i += 2) {
            int s0 = g_srcs[i], s1 = g_srcs[i + 1];
            uint4 k0 = ((const uint4*)&g_kb[(size_t)s0 * QK])[lane];
            uint4 k1 = ((const uint4*)&g_kb[(size_t)s1 * QK])[lane];
            uint4 v0 = ((const uint4*)&g_vb[(size_t)s0 * QK])[lane];
            uint4 v1 = ((const uint4*)&g_vb[(size_t)s1 * QK])[lane];
            float p0 = dot2bf(q.x, k0.x) + dot2bf(q.y, k0.y) + dot2bf(q.z, k0.z) + dot2bf(q.w, k0.w);
            float p1 = dot2bf(q.x, k1.x) + dot2bf(q.y, k1.y) + dot2bf(q.z, k1.z) + dot2bf(q.w, k1.w);
            p0 += __shfl_xor_sync(0xffffffffu, p0, 1);
            p1 += __shfl_xor_sync(0xffffffffu, p1, 1);
            p0 += __shfl_xor_sync(0xffffffffu, p0, 2);
            p1 += __shfl_xor_sync(0xffffffffu, p1, 2);
            p0 += __shfl_xor_sync(0xffffffffu, p0, 4);
            p1 += __shfl_xor_sync(0xffffffffu, p1, 4);
            float e0 = __expf(p0 * 0.125f);
            float e1 = __expf(p1 * 0.125f);
            z += e0 + e1;
            const uint32_t* u0 = (const uint32_t*)&v0;
            const uint32_t* u1 = (const uint32_t*)&v1;
            #pragma unroll
            for (int j = 0; j < 4; j++) {
                acc[2 * j]     += e0 * bflo(u0[j]) + e1 * bflo(u1[j]);
                acc[2 * j + 1] += e0 * bfhi(u0[j]) + e1 * bfhi(u1[j]);
            }
        }
        if (i < e) {
            int s0 = g_srcs[i];
            uint4 k0 = ((const uint4*)&g_kb[(size_t)s0 * QK])[lane];
            uint4 v0 = ((const uint4*)&g_vb[(size_t)s0 * QK])[lane];
            float p0 = dot2bf(q.x, k0.x) + dot2bf(q.y, k0.y) + dot2bf(q.z, k0.z) + dot2bf(q.w, k0.w);
            p0 += __shfl_xor_sync(0xffffffffu, p0, 1);
            p0 += __shfl_xor_sync(0xffffffffu, p0, 2);
            p0 += __shfl_xor_sync(0xffffffffu, p0, 4);
            float e0 = __expf(p0 * 0.125f);
            z += e0;
            const uint32_t* u0 = (const uint32_t*)&v0;
            #pragma unroll
            for (int j = 0; j < 4; j++) {
                acc[2 * j]     += e0 * bflo(u0[j]);
                acc[2 * j + 1] += e0 * bfhi(u0[j]);
            }
        }
    }

    // combine partials: odd warp publishes, even warp consumes
    if (half == 1) {
        #pragma unroll
        for (int j = 0; j < 8; j++) s_acc[nl][lane][j] = acc[j];
        s_z[nl][lane] = z;
    }
    __syncthreads();
    if (half == 1 || !active) return;

    z += s_z[nl][lane];
    #pragma unroll
    for (int j = 0; j < 8; j++) acc[j] += s_acc[nl][lane][j];

    float w = (end > beg) ? (0.25f / z) : 0.f;
    #pragma unroll
    for (int j = 0; j < 8; j++) {
        float a = acc[j] * w;
        a += __shfl_xor_sync(0xffffffffu, a, 8);
        a += __shfl_xor_sync(0xffffffffu, a, 16);
        acc[j] = a;
    }

    if (lane < 8) {
        const float* sp = &g_skip[(size_t)node * HID + lane * 8];
        float4 s0 = *(const float4*)sp;
        float4 s1 = *(const float4*)(sp + 4);
        float o[8];
        o[0] = fmaxf(acc[0] + s0.x, 0.f);
        o[1] = fmaxf(acc[1] + s0.y, 0.f);
        o[2] = fmaxf(acc[2] + s0.z, 0.f);
        o[3] = fmaxf(acc[3] + s0.w, 0.f);
        o[4] = fmaxf(acc[4] + s1.x, 0.f);
        o[5] = fmaxf(acc[5] + s1.y, 0.f);
        o[6] = fmaxf(acc[6] + s1.z, 0.f);
        o[7] = fmaxf(acc[7] + s1.w, 0.f);
        if (OUT_BF) {
            uint4 pb;
            pb.x = pack_bf16(o[0], o[1]);
            pb.y = pack_bf16(o[2], o[3]);
            pb.z = pack_bf16(o[4], o[5]);
            pb.w = pack_bf16(o[6], o[7]);
            *(uint4*)&((__nv_bfloat16*)outp)[(size_t)node * HID + lane * 8] = pb;
        } else {
            float* op = &((float*)outp)[(size_t)node * HID + lane * 8];
            *(float4*)op       = make_float4(o[0], o[1], o[2], o[3]);
            *(float4*)(op + 4) = make_float4(o[4], o[5], o[6], o[7]);
        }
    }
}

// ---------------- pool: per-graph mean of g_h2 (batch is sorted), 64 nodes/block ------
__global__ void pool_kernel(const int* __restrict__ batch, int N) {
    const int NPB = 64;
    int d = threadIdx.x;
    int n0 = blockIdx.x * NPB;
    int n1 = min(n0 + NPB, N);
    float acc = 0.f, cnt = 0.f;
    int cur = -1;
    for (int n = n0; n < n1; n++) {
        int g = batch[n];
        if (g != cur) {
            if (cur >= 0) {
                atomicAdd(&g_gsum[cur * HID + d], acc);
                if (d == 0) atomicAdd(&g_gcnt[cur], cnt);
            }
            cur = g; acc = 0.f; cnt = 0.f;
        }
        acc += g_h2[(size_t)n * HID + d];
        cnt += 1.f;
    }
    if (cur >= 0) {
        atomicAdd(&g_gsum[cur * HID + d], acc);
        if (d == 0) atomicAdd(&g_gcnt[cur], cnt);
    }
}

// ---------------- head: one block per graph ----------------
__global__ void __launch_bounds__(128, 8) head_kernel(
        const float* __restrict__ gf,
        const float* __restrict__ gW1, const float* __restrict__ gb1,
        const float* __restrict__ gW2, const float* __restrict__ gb2,
        const float* __restrict__ hW1, const float* __restrict__ hb1,
        const float* __restrict__ hW2, const float* __restrict__ hb2,
        float* __restrict__ out) {
    __shared__ float s_gf[GDIM];
    __shared__ float s_patch[HID];
    __shared__ float s_g1[HID];
    __shared__ float s_g2[HID];
    __shared__ float s_hid[HID];
    int g = blockIdx.x;
    int t = threadIdx.x;

    for (int i = t; i < GDIM; i += 128) s_gf[i] = gf[g * GDIM + i];
    if (t < HID) s_patch[t] = g_gsum[g * HID + t] / fmaxf(g_gcnt[g], 1.f);
    __syncthreads();

    {
        int j = t >> 1, half = t & 1;
        float s = 0.f;
        int kb = half * 128;
        #pragma unroll 8
        for (int k = 0; k < 128; k++) s += s_gf[kb + k] * gW1[(kb + k) * HID + j];
        s += __shfl_xor_sync(0xffffffffu, s, 1);
        if (half == 0) s_g1[j] = fmaxf(s + gb1[j], 0.f);
    }
    __syncthreads();

    if (t < HID) {
        float s = gb2[t];
        #pragma unroll 8
        for (int k = 0; k < HID; k++) s += s_g1[k] * gW2[k * HID + t];
        s_g2[t] = fmaxf(s, 0.f);
    }
    __syncthreads();

    {
        int j = t >> 1, half = t & 1;
        float s = 0.f;
        const float* src = half ? s_g2 : s_patch;
        int kb = half * HID;
        #pragma unroll 8
        for (int k = 0; k < HID; k++) s += src[k] * hW1[(kb + k) * HID + j];
        s += __shfl_xor_sync(0xffffffffu, s, 1);
        if (half == 0) s_hid[j] = fmaxf(s + hb1[j], 0.f);
    }
    __syncthreads();

    if (t < NCLS) {
        float s = hb2[t];
        #pragma unroll 8
        for (int k = 0; k < HID; k++) s += s_hid[k] * hW2[k * NCLS + t];
        out[g * NCLS + t] = s;
    }
}

// ---------------- host orchestration ----------------
extern "C" void kernel_launch(void* const* d_in, const int* in_sizes, int n_in,
                              void* d_out, int out_size) {
    const float* x     = (const float*)d_in[0];
    const int*   ei    = (const int*)  d_in[1];
    const int*   batch = (const int*)  d_in[2];
    const float* gf    = (const float*)d_in[3];
    const float* c1[8]; for (int i = 0; i < 8; i++) c1[i] = (const float*)d_in[4 + i];
    const float* c2[8]; for (int i = 0; i < 8; i++) c2[i] = (const float*)d_in[12 + i];
    const float* gW1 = (const float*)d_in[20]; const float* gb1 = (const float*)d_in[21];
    const float* gW2 = (const float*)d_in[22]; const float* gb2 = (const float*)d_in[23];
    const float* hW1 = (const float*)d_in[24]; const float* hb1 = (const float*)d_in[25];
    const float* hW2 = (const float*)d_in[26]; const float* hb2 = (const float*)d_in[27];

    int N = in_sizes[0] / 128;
    int E = in_sizes[1] / 2;

    void *p_h1b, *p_h2, *p_gsum, *p_gcnt, *p_cursor;
    cudaGetSymbolAddress(&p_h1b,    g_h1b);
    cudaGetSymbolAddress(&p_h2,     g_h2);
    cudaGetSymbolAddress(&p_gsum,   g_gsum);
    cudaGetSymbolAddress(&p_gcnt,   g_gcnt);
    cudaGetSymbolAddress(&p_cursor, g_cursor);

    // ---- build CSR once (reused by both convs) ----
    cudaMemsetAsync(p_cursor, 0, (size_t)N * sizeof(int), 0);
    hist_kernel<<<(E + 255) / 256, 256>>>(ei, E);
    scan_kernel<<<1, 1024>>>(N, E);
    scatter_kernel<<<(E + 255) / 256, 256>>>(ei, E);

    dim3 gg((N + 127) / 128, OCT / 64);
    int fe_grid = (N + 3) / 4;

    // conv1 (in=128, fp32 input, bf16 output)
    pack_w<<<(128 * OCT + 255) / 256, 256>>>(c1[0], c1[1], c1[2], c1[3],
                                             c1[4], c1[5], c1[6], c1[7], 128);
    gemm_qkvs<0><<<gg, 256>>>(x, N, 128);
    fused_edge<1><<<fe_grid, 256>>>(p_h1b, N);

    // conv2 (in=64, bf16 input, fp32 output)
    pack_w<<<(64 * OCT + 255) / 256, 256>>>(c2[0], c2[1], c2[2], c2[3],
                                            c2[4], c2[5], c2[6], c2[7], 64);
    gemm_qkvs<1><<<gg, 256>>>(p_h1b, N, 64);
    fused_edge<0><<<fe_grid, 256>>>(p_h2, N);

    // pooling
    cudaMemsetAsync(p_gsum, 0, NGRAPH * HID * sizeof(float), 0);
    cudaMemsetAsync(p_gcnt, 0, NGRAPH * sizeof(float), 0);
    pool_kernel<<<(N + 63) / 64, HID>>>(batch, N);

    // head (one block per graph)
    head_kernel<<<NGRAPH, 128>>>(gf, gW1, gb1, gW2, gb2, hW1, hb1, hW2, hb2, (float*)d_out);
}

// round 15
// speedup vs baseline: 1.1306x; 1.1306x over previous
#include <cuda_runtime.h>
#include <cuda_bf16.h>
#include <math.h>
#include <cstdint>

// Problem constants
#define NMAX   50000
#define EMAX   800000
#define HEADS  4
#define HID    64
#define QK     256        // HEADS*HID
#define OCT    832        // 3*QK + HID
#define NGRAPH 64
#define GDIM   256
#define NCLS   10

// ---------------- scratch (device globals; no runtime allocation) ----------------
__device__ __align__(16) __nv_bfloat16 g_qb[NMAX * QK];   // bf16 q
__device__ __align__(16) __nv_bfloat16 g_kb[NMAX * QK];   // bf16 k
__device__ __align__(16) __nv_bfloat16 g_vb[NMAX * QK];   // bf16 v
__device__ __align__(16) float    g_skip[NMAX * HID];
__device__ __align__(16) __nv_bfloat16 g_h1b[NMAX * HID]; // conv1 out (bf16 = GEMM2's A)
__device__ __align__(16) float    g_h2  [NMAX * HID];
__device__ __align__(16) float    g_Wc  [128 * OCT];
__device__ __align__(16) float    g_bc  [OCT];
__device__ __align__(16) float    g_gsum[NGRAPH * HID];
__device__ __align__(16) float    g_gcnt[NGRAPH];
// CSR (dst-sorted) graph, built once per launch
__device__ __align__(16) int      g_rowptr[NMAX + 1];
__device__ __align__(16) int      g_cursor[NMAX];
__device__ __align__(16) int      g_srcs  [EMAX];

// ---------------- helpers ----------------
__device__ __forceinline__ uint32_t pack_bf16(float a, float b) {
    __nv_bfloat16 ha = __float2bfloat16_rn(a);
    __nv_bfloat16 hb = __float2bfloat16_rn(b);
    return (uint32_t)__bfloat16_as_ushort(ha) | ((uint32_t)__bfloat16_as_ushort(hb) << 16);
}
__device__ __forceinline__ float bf_hi_res(float v) {   // v - bf16(v)
    return v - __bfloat162float(__float2bfloat16_rn(v));
}
__device__ __forceinline__ float bflo(uint32_t u) { return __uint_as_float(u << 16); }
__device__ __forceinline__ float bfhi(uint32_t u) { return __uint_as_float(u & 0xffff0000u); }
__device__ __forceinline__ float dot2bf(uint32_t ua, uint32_t ub) {
    return bflo(ua) * bflo(ub) + bfhi(ua) * bfhi(ub);
}

#define MMA_BF16(c, a, b)                                                     \
    asm volatile("mma.sync.aligned.m16n8k16.row.col.f32.bf16.bf16.f32 "       \
                 "{%0,%1,%2,%3}, {%4,%5,%6,%7}, {%8,%9}, {%0,%1,%2,%3};"      \
                 : "+f"((c)[0]), "+f"((c)[1]), "+f"((c)[2]), "+f"((c)[3])     \
                 : "r"((a)[0]), "r"((a)[1]), "r"((a)[2]), "r"((a)[3]),        \
                   "r"((b)[0]), "r"((b)[1]))

// ---------------- CSR build ----------------
__global__ void hist_kernel(const int* __restrict__ ei, int E) {
    int e = blockIdx.x * blockDim.x + threadIdx.x;
    if (e < E) atomicAdd(&g_cursor[ei[E + e]], 1);
}
__global__ void scan_kernel(int N, int E) {
    __shared__ int s_part[1024];
    int t = threadIdx.x;
    int chunk = (N + 1023) >> 10;
    int b = t * chunk, en = min(b + chunk, N);
    int sum = 0;
    for (int i = b; i < en; i++) sum += g_cursor[i];
    s_part[t] = sum;
    __syncthreads();
    for (int off = 1; off < 1024; off <<= 1) {
        int v = (t >= off) ? s_part[t - off] : 0;
        __syncthreads();
        s_part[t] += v;
        __syncthreads();
    }
    int run = s_part[t] - sum;   // exclusive base
    for (int i = b; i < en; i++) {
        int c = g_cursor[i];
        g_rowptr[i] = run;
        g_cursor[i] = run;
        run += c;
    }
    if (t == 0) g_rowptr[N] = E;
}
__global__ void scatter_kernel(const int* __restrict__ ei, int E) {
    int e = blockIdx.x * blockDim.x + threadIdx.x;
    if (e >= E) return;
    int src = ei[e], dst = ei[E + e];
    int pos = atomicAdd(&g_cursor[dst], 1);
    g_srcs[pos] = src;
}

// ---------------- weight pack ----------------
__global__ void pack_w(const float* __restrict__ Wq, const float* __restrict__ bq,
                       const float* __restrict__ Wk, const float* __restrict__ bk,
                       const float* __restrict__ Wv, const float* __restrict__ bv,
                       const float* __restrict__ Ws, const float* __restrict__ bs, int K) {
    int idx = blockIdx.x * blockDim.x + threadIdx.x;
    int tot = K * OCT;
    if (idx < tot) {
        int k = idx / OCT, j = idx - k * OCT;
        float v;
        if      (j < 256) v = Wq[k * 256 + j];
        else if (j < 512) v = Wk[k * 256 + (j - 256)];
        else if (j < 768) v = Wv[k * 256 + (j - 512)];
        else              v = Ws[k * 64  + (j - 768)];
        g_Wc[idx] = v;
    }
    if (idx < OCT) {
        float b;
        if      (idx < 256) b = bq[idx];
        else if (idx < 512) b = bk[idx - 256];
        else if (idx < 768) b = bv[idx - 512];
        else                b = bs[idx - 768];
        g_bc[idx] = b;
    }
}

// ---------------- GEMM: bf16 mma.sync.m16n8k16 ------------------------------------
// B hi/lo split (2-term) ONLY for the skip block (y==12, fp32 out, systematic-error
// sensitive). q/k/v blocks are stored bf16 anyway, so storage rounding dominates and
// the B-lo term is skipped -> ~46% fewer MMAs.
#define ASTR32 136
#define BSTR32 72
template<int IN_BF>
__global__ void __launch_bounds__(256, 2) gemm_qkvs(const void* __restrict__ Ap, int N, int K) {
    __shared__ uint32_t As[8 * ASTR32];      // [kpair][m]
    __shared__ uint32_t Bs[2][8 * BSTR32];   // [hi/lo][kpair][n]
    const int t    = threadIdx.x;
    const int lane = t & 31, wid = t >> 5;
    const int warp_m = wid & 3;
    const int warp_n = wid >> 2;
    const int row0 = blockIdx.x * 128, col0 = blockIdx.y * 64;
    const int lq = lane >> 2;
    const int lr = lane & 3;
    const bool need_lo = (blockIdx.y == 12);   // only skip block needs the B residual

    float c[2][4][4];
    #pragma unroll
    for (int mt = 0; mt < 2; mt++)
        #pragma unroll
        for (int nt = 0; nt < 4; nt++)
            #pragma unroll
            for (int i = 0; i < 4; i++) c[mt][nt][i] = 0.f;

    for (int k0 = 0; k0 < K; k0 += 16) {
        if (IN_BF) {
            const __nv_bfloat16* A = (const __nv_bfloat16*)Ap;
            int r = t >> 1, half = t & 1;
            int gr = row0 + r;
            uint4 a = (gr < N) ? *(const uint4*)&A[(size_t)gr * K + k0 + half * 8]
                               : make_uint4(0u, 0u, 0u, 0u);
            int kp = half * 4;
            As[(kp + 0) * ASTR32 + r] = a.x;
            As[(kp + 1) * ASTR32 + r] = a.y;
            As[(kp + 2) * ASTR32 + r] = a.z;
            As[(kp + 3) * ASTR32 + r] = a.w;
        } else {
            const float* A = (const float*)Ap;
            #pragma unroll
            for (int ii = 0; ii < 2; ii++) {
                int idx = t + ii * 256;
                int r = idx >> 2, cg = (idx & 3) << 2;
                int gr = row0 + r;
                float4 a = (gr < N) ? *(const float4*)&A[(size_t)gr * K + k0 + cg]
                                    : make_float4(0.f, 0.f, 0.f, 0.f);
                int kp = cg >> 1;
                As[kp * ASTR32 + r]       = pack_bf16(a.x, a.y);
                As[(kp + 1) * ASTR32 + r] = pack_bf16(a.z, a.w);
            }
        }
        if (t < 128) {
            int kp = t >> 4, j4 = (t & 15) << 2;
            const float* r0p = &g_Wc[(size_t)(k0 + 2 * kp) * OCT + col0 + j4];
            const float* r1p = r0p + OCT;
            float4 b0 = *(const float4*)r0p;
            float4 b1 = *(const float4*)r1p;
            float v0[4] = {b0.x, b0.y, b0.z, b0.w};
            float v1[4] = {b1.x, b1.y, b1.z, b1.w};
            #pragma unroll
            for (int i = 0; i < 4; i++) {
                Bs[0][kp * BSTR32 + j4 + i] = pack_bf16(v0[i], v1[i]);
                if (need_lo)
                    Bs[1][kp * BSTR32 + j4 + i] = pack_bf16(bf_hi_res(v0[i]), bf_hi_res(v1[i]));
            }
        }
        __syncthreads();

        uint32_t ah[2][4];
        #pragma unroll
        for (int mt = 0; mt < 2; mt++) {
            int r0 = warp_m * 32 + mt * 16 + lq;
            ah[mt][0] = As[lr * ASTR32 + r0];
            ah[mt][1] = As[lr * ASTR32 + r0 + 8];
            ah[mt][2] = As[(lr + 4) * ASTR32 + r0];
            ah[mt][3] = As[(lr + 4) * ASTR32 + r0 + 8];
        }
        uint32_t bh[4][2];
        #pragma unroll
        for (int nt = 0; nt < 4; nt++) {
            int n = warp_n * 32 + nt * 8 + lq;
            bh[nt][0] = Bs[0][lr * BSTR32 + n];
            bh[nt][1] = Bs[0][(lr + 4) * BSTR32 + n];
        }
        #pragma unroll
        for (int mt = 0; mt < 2; mt++)
            #pragma unroll
            for (int nt = 0; nt < 4; nt++)
                MMA_BF16(c[mt][nt], ah[mt], bh[nt]);
        if (need_lo) {
            uint32_t bl[4][2];
            #pragma unroll
            for (int nt = 0; nt < 4; nt++) {
                int n = warp_n * 32 + nt * 8 + lq;
                bl[nt][0] = Bs[1][lr * BSTR32 + n];
                bl[nt][1] = Bs[1][(lr + 4) * BSTR32 + n];
            }
            #pragma unroll
            for (int mt = 0; mt < 2; mt++)
                #pragma unroll
                for (int nt = 0; nt < 4; nt++)
                    MMA_BF16(c[mt][nt], ah[mt], bl[nt]);
        }
        __syncthreads();
    }

    int y = blockIdx.y;
    bool is_bf = (y < 12);
    __nv_bfloat16* bfdst; int bfoff;
    if      (y < 4) { bfdst = g_qb; bfoff = col0;       }
    else if (y < 8) { bfdst = g_kb; bfoff = col0 - 256; }
    else            { bfdst = g_vb; bfoff = col0 - 512; }

    #pragma unroll
    for (int mt = 0; mt < 2; mt++) {
        int r = row0 + warp_m * 32 + mt * 16 + lq;
        #pragma unroll
        for (int nt = 0; nt < 4; nt++) {
            int jc_in = warp_n * 32 + nt * 8 + lr * 2;
            float b0 = g_bc[col0 + jc_in];
            float b1 = g_bc[col0 + jc_in + 1];
            if (is_bf) {
                if (r < N) {
                    *(uint32_t*)&bfdst[(size_t)r * 256 + bfoff + jc_in] =
                        pack_bf16(c[mt][nt][0] + b0, c[mt][nt][1] + b1);
                }
                if (r + 8 < N) {
                    *(uint32_t*)&bfdst[(size_t)(r + 8) * 256 + bfoff + jc_in] =
                        pack_bf16(c[mt][nt][2] + b0, c[mt][nt][3] + b1);
                }
            } else {
                if (r < N) {
                    float2 o = make_float2(c[mt][nt][0] + b0, c[mt][nt][1] + b1);
                    *(float2*)&g_skip[(size_t)r * 64 + jc_in] = o;
                }
                if (r + 8 < N) {
                    float2 o = make_float2(c[mt][nt][2] + b0, c[mt][nt][3] + b1);
                    *(float2*)&g_skip[(size_t)(r + 8) * 64 + jc_in] = o;
                }
            }
        }
    }
}

// ---------------- fused edge conv: warp per dst node, 2-edge unrolled ----------------
template<int OUT_BF>
__global__ void __launch_bounds__(256, 4) fused_edge(void* __restrict__ outp, int N) {
    int node = (blockIdx.x * blockDim.x + threadIdx.x) >> 5;
    int lane = threadIdx.x & 31;
    if (node >= N) return;

    uint4 q = ((const uint4*)&g_qb[(size_t)node * QK])[lane];
    int beg = g_rowptr[node], end = g_rowptr[node + 1];

    float z = 0.f;
    float acc[8] = {0.f, 0.f, 0.f, 0.f, 0.f, 0.f, 0.f, 0.f};

    int i = beg;
    for (; i + 2 <= end; i += 2) {
        int s0 = g_srcs[i], s1 = g_srcs[i + 1];
        uint4 k0 = ((const uint4*)&g_kb[(size_t)s0 * QK])[lane];
        uint4 k1 = ((const uint4*)&g_kb[(size_t)s1 * QK])[lane];
        uint4 v0 = ((const uint4*)&g_vb[(size_t)s0 * QK])[lane];
        uint4 v1 = ((const uint4*)&g_vb[(size_t)s1 * QK])[lane];
        float p0 = dot2bf(q.x, k0.x) + dot2bf(q.y, k0.y) + dot2bf(q.z, k0.z) + dot2bf(q.w, k0.w);
        float p1 = dot2bf(q.x, k1.x) + dot2bf(q.y, k1.y) + dot2bf(q.z, k1.z) + dot2bf(q.w, k1.w);
        p0 += __shfl_xor_sync(0xffffffffu, p0, 1);
        p1 += __shfl_xor_sync(0xffffffffu, p1, 1);
        p0 += __shfl_xor_sync(0xffffffffu, p0, 2);
        p1 += __shfl_xor_sync(0xffffffffu, p1, 2);
        p0 += __shfl_xor_sync(0xffffffffu, p0, 4);
        p1 += __shfl_xor_sync(0xffffffffu, p1, 4);
        float e0 = __expf(p0 * 0.125f);
        float e1 = __expf(p1 * 0.125f);
        z += e0 + e1;
        const uint32_t* u0 = (const uint32_t*)&v0;
        const uint32_t* u1 = (const uint32_t*)&v1;
        #pragma unroll
        for (int j = 0; j < 4; j++) {
            acc[2 * j]     += e0 * bflo(u0[j]) + e1 * bflo(u1[j]);
            acc[2 * j + 1] += e0 * bfhi(u0[j]) + e1 * bfhi(u1[j]);
        }
    }
    if (i < end) {
        int s0 = g_srcs[i];
        uint4 k0 = ((const uint4*)&g_kb[(size_t)s0 * QK])[lane];
        uint4 v0 = ((const uint4*)&g_vb[(size_t)s0 * QK])[lane];
        float p0 = dot2bf(q.x, k0.x) + dot2bf(q.y, k0.y) + dot2bf(q.z, k0.z) + dot2bf(q.w, k0.w);
        p0 += __shfl_xor_sync(0xffffffffu, p0, 1);
        p0 += __shfl_xor_sync(0xffffffffu, p0, 2);
        p0 += __shfl_xor_sync(0xffffffffu, p0, 4);
        float e0 = __expf(p0 * 0.125f);
        z += e0;
        const uint32_t* u0 = (const uint32_t*)&v0;
        #pragma unroll
        for (int j = 0; j < 4; j++) {
            acc[2 * j]     += e0 * bflo(u0[j]);
            acc[2 * j + 1] += e0 * bfhi(u0[j]);
        }
    }

    float w = (end > beg) ? (0.25f / z) : 0.f;
    #pragma unroll
    for (int j = 0; j < 8; j++) {
        float a = acc[j] * w;
        a += __shfl_xor_sync(0xffffffffu, a, 8);
        a += __shfl_xor_sync(0xffffffffu, a, 16);
        acc[j] = a;
    }

    if (lane < 8) {
        const float* sp = &g_skip[(size_t)node * HID + lane * 8];
        float4 s0 = *(const float4*)sp;
        float4 s1 = *(const float4*)(sp + 4);
        float o[8];
        o[0] = fmaxf(acc[0] + s0.x, 0.f);
        o[1] = fmaxf(acc[1] + s0.y, 0.f);
        o[2] = fmaxf(acc[2] + s0.z, 0.f);
        o[3] = fmaxf(acc[3] + s0.w, 0.f);
        o[4] = fmaxf(acc[4] + s1.x, 0.f);
        o[5] = fmaxf(acc[5] + s1.y, 0.f);
        o[6] = fmaxf(acc[6] + s1.z, 0.f);
        o[7] = fmaxf(acc[7] + s1.w, 0.f);
        if (OUT_BF) {
            uint4 pb;
            pb.x = pack_bf16(o[0], o[1]);
            pb.y = pack_bf16(o[2], o[3]);
            pb.z = pack_bf16(o[4], o[5]);
            pb.w = pack_bf16(o[6], o[7]);
            *(uint4*)&((__nv_bfloat16*)outp)[(size_t)node * HID + lane * 8] = pb;
        } else {
            float* op = &((float*)outp)[(size_t)node * HID + lane * 8];
            *(float4*)op       = make_float4(o[0], o[1], o[2], o[3]);
            *(float4*)(op + 4) = make_float4(o[4], o[5], o[6], o[7]);
        }
    }
}

// ---------------- pool: per-graph mean of g_h2 (batch is sorted), 64 nodes/block ------
__global__ void pool_kernel(const int* __restrict__ batch, int N) {
    const int NPB = 64;
    int d = threadIdx.x;
    int n0 = blockIdx.x * NPB;
    int n1 = min(n0 + NPB, N);
    float acc = 0.f, cnt = 0.f;
    int cur = -1;
    for (int n = n0; n < n1; n++) {
        int g = batch[n];
        if (g != cur) {
            if (cur >= 0) {
                atomicAdd(&g_gsum[cur * HID + d], acc);
                if (d == 0) atomicAdd(&g_gcnt[cur], cnt);
            }
            cur = g; acc = 0.f; cnt = 0.f;
        }
        acc += g_h2[(size_t)n * HID + d];
        cnt += 1.f;
    }
    if (cur >= 0) {
        atomicAdd(&g_gsum[cur * HID + d], acc);
        if (d == 0) atomicAdd(&g_gcnt[cur], cnt);
    }
}

// ---------------- head: one block per graph ----------------
__global__ void __launch_bounds__(128, 8) head_kernel(
        const float* __restrict__ gf,
        const float* __restrict__ gW1, const float* __restrict__ gb1,
        const float* __restrict__ gW2, const float* __restrict__ gb2,
        const float* __restrict__ hW1, const float* __restrict__ hb1,
        const float* __restrict__ hW2, const float* __restrict__ hb2,
        float* __restrict__ out) {
    __shared__ float s_gf[GDIM];
    __shared__ float s_patch[HID];
    __shared__ float s_g1[HID];
    __shared__ float s_g2[HID];
    __shared__ float s_hid[HID];
    int g = blockIdx.x;
    int t = threadIdx.x;

    for (int i = t; i < GDIM; i += 128) s_gf[i] = gf[g * GDIM + i];
    if (t < HID) s_patch[t] = g_gsum[g * HID + t] / fmaxf(g_gcnt[g], 1.f);
    __syncthreads();

    {
        int j = t >> 1, half = t & 1;
        float s = 0.f;
        int kb = half * 128;
        #pragma unroll 8
        for (int k = 0; k < 128; k++) s += s_gf[kb + k] * gW1[(kb + k) * HID + j];
        s += __shfl_xor_sync(0xffffffffu, s, 1);
        if (half == 0) s_g1[j] = fmaxf(s + gb1[j], 0.f);
    }
    __syncthreads();

    if (t < HID) {
        float s = gb2[t];
        #pragma unroll 8
        for (int k = 0; k < HID; k++) s += s_g1[k] * gW2[k * HID + t];
        s_g2[t] = fmaxf(s, 0.f);
    }
    __syncthreads();

    {
        int j = t >> 1, half = t & 1;
        float s = 0.f;
        const float* src = half ? s_g2 : s_patch;
        int kb = half * HID;
        #pragma unroll 8
        for (int k = 0; k < HID; k++) s += src[k] * hW1[(kb + k) * HID + j];
        s += __shfl_xor_sync(0xffffffffu, s, 1);
        if (half == 0) s_hid[j] = fmaxf(s + hb1[j], 0.f);
    }
    __syncthreads();

    if (t < NCLS) {
        float s = hb2[t];
        #pragma unroll 8
        for (int k = 0; k < HID; k++) s += s_hid[k] * hW2[k * NCLS + t];
        out[g * NCLS + t] = s;
    }
}

// ---------------- host orchestration ----------------
extern "C" void kernel_launch(void* const* d_in, const int* in_sizes, int n_in,
                              void* d_out, int out_size) {
    const float* x     = (const float*)d_in[0];
    const int*   ei    = (const int*)  d_in[1];
    const int*   batch = (const int*)  d_in[2];
    const float* gf    = (const float*)d_in[3];
    const float* c1[8]; for (int i = 0; i < 8; i++) c1[i] = (const float*)d_in[4 + i];
    const float* c2[8]; for (int i = 0; i < 8; i++) c2[i] = (const float*)d_in[12 + i];
    const float* gW1 = (const float*)d_in[20]; const float* gb1 = (const float*)d_in[21];
    const float* gW2 = (const float*)d_in[22]; const float* gb2 = (const float*)d_in[23];
    const float* hW1 = (const float*)d_in[24]; const float* hb1 = (const float*)d_in[25];
    const float* hW2 = (const float*)d_in[26]; const float* hb2 = (const float*)d_in[27];

    int N = in_sizes[0] / 128;
    int E = in_sizes[1] / 2;

    void *p_h1b, *p_h2, *p_gsum, *p_gcnt, *p_cursor;
    cudaGetSymbolAddress(&p_h1b,    g_h1b);
    cudaGetSymbolAddress(&p_h2,     g_h2);
    cudaGetSymbolAddress(&p_gsum,   g_gsum);
    cudaGetSymbolAddress(&p_gcnt,   g_gcnt);
    cudaGetSymbolAddress(&p_cursor, g_cursor);

    // ---- build CSR once (reused by both convs) ----
    cudaMemsetAsync(p_cursor, 0, (size_t)N * sizeof(int), 0);
    hist_kernel<<<(E + 255) / 256, 256>>>(ei, E);
    scan_kernel<<<1, 1024>>>(N, E);
    scatter_kernel<<<(E + 255) / 256, 256>>>(ei, E);

    dim3 gg((N + 127) / 128, OCT / 64);

    // conv1 (in=128, fp32 input, bf16 output)
    pack_w<<<(128 * OCT + 255) / 256, 256>>>(c1[0], c1[1], c1[2], c1[3],
                                             c1[4], c1[5], c1[6], c1[7], 128);
    gemm_qkvs<0><<<gg, 256>>>(x, N, 128);
    fused_edge<1><<<(N * 32 + 255) / 256, 256>>>(p_h1b, N);

    // conv2 (in=64, bf16 input, fp32 output)
    pack_w<<<(64 * OCT + 255) / 256, 256>>>(c2[0], c2[1], c2[2], c2[3],
                                            c2[4], c2[5], c2[6], c2[7], 64);
    gemm_qkvs<1><<<gg, 256>>>(p_h1b, N, 64);
    fused_edge<0><<<(N * 32 + 255) / 256, 256>>>(p_h2, N);

    // pooling
    cudaMemsetAsync(p_gsum, 0, NGRAPH * HID * sizeof(float), 0);
    cudaMemsetAsync(p_gcnt, 0, NGRAPH * sizeof(float), 0);
    pool_kernel<<<(N + 63) / 64, HID>>>(batch, N);

    // head (one block per graph)
    head_kernel<<<NGRAPH, 128>>>(gf, gW1, gb1, gW2, gb2, hW1, hb1, hW2, hb2, (float*)d_out);
}

// round 16
// speedup vs baseline: 1.1528x; 1.0197x over previous
#include <cuda_runtime.h>
#include <cuda_bf16.h>
#include <math.h>
#include <cstdint>

// Problem constants
#define NMAX   50000
#define EMAX   800000
#define HEADS  4
#define HID    64
#define QK     256        // HEADS*HID
#define OCT    832        // 3*QK + HID
#define NGRAPH 64
#define GDIM   256
#define NCLS   10

// ---------------- scratch (device globals; no runtime allocation) ----------------
__device__ __align__(16) __nv_bfloat16 g_xb[NMAX * 128];  // bf16 copy of x (conv1 A)
__device__ __align__(16) __nv_bfloat16 g_qb[NMAX * QK];   // bf16 q
__device__ __align__(16) __nv_bfloat16 g_kb[NMAX * QK];   // bf16 k
__device__ __align__(16) __nv_bfloat16 g_vb[NMAX * QK];   // bf16 v
__device__ __align__(16) float    g_skip[NMAX * HID];
__device__ __align__(16) __nv_bfloat16 g_h1b[NMAX * HID]; // conv1 out (bf16 = GEMM2's A)
__device__ __align__(16) float    g_h2  [NMAX * HID];
__device__ __align__(16) uint32_t g_Bph[13 * 64 * 64];    // packed bf16 B (hi), [y][kp][n]
__device__ __align__(16) uint32_t g_Bpl[64 * 64];         // packed bf16 B (lo), skip block only
__device__ __align__(16) float    g_bc  [OCT];
__device__ __align__(16) float    g_gsum[NGRAPH * HID];
__device__ __align__(16) float    g_gcnt[NGRAPH];
// CSR (dst-sorted) graph, built once per launch
__device__ __align__(16) int      g_rowptr[NMAX + 1];
__device__ __align__(16) int      g_cursor[NMAX];
__device__ __align__(16) int      g_srcs  [EMAX];

// ---------------- helpers ----------------
__device__ __forceinline__ uint32_t pack_bf16(float a, float b) {
    __nv_bfloat16 ha = __float2bfloat16_rn(a);
    __nv_bfloat16 hb = __float2bfloat16_rn(b);
    return (uint32_t)__bfloat16_as_ushort(ha) | ((uint32_t)__bfloat16_as_ushort(hb) << 16);
}
__device__ __forceinline__ float bf_hi_res(float v) {   // v - bf16(v)
    return v - __bfloat162float(__float2bfloat16_rn(v));
}
__device__ __forceinline__ float bflo(uint32_t u) { return __uint_as_float(u << 16); }
__device__ __forceinline__ float bfhi(uint32_t u) { return __uint_as_float(u & 0xffff0000u); }
__device__ __forceinline__ float dot2bf(uint32_t ua, uint32_t ub) {
    return bflo(ua) * bflo(ub) + bfhi(ua) * bfhi(ub);
}

#define MMA_BF16(c, a, b)                                                     \
    asm volatile("mma.sync.aligned.m16n8k16.row.col.f32.bf16.bf16.f32 "       \
                 "{%0,%1,%2,%3}, {%4,%5,%6,%7}, {%8,%9}, {%0,%1,%2,%3};"      \
                 : "+f"((c)[0]), "+f"((c)[1]), "+f"((c)[2]), "+f"((c)[3])     \
                 : "r"((a)[0]), "r"((a)[1]), "r"((a)[2]), "r"((a)[3]),        \
                   "r"((b)[0]), "r"((b)[1]))

// ---------------- CSR build ----------------
__global__ void hist_kernel(const int* __restrict__ ei, int E) {
    int e = blockIdx.x * blockDim.x + threadIdx.x;
    if (e < E) atomicAdd(&g_cursor[ei[E + e]], 1);
}
__global__ void scan_kernel(int N, int E) {
    __shared__ int s_part[1024];
    int t = threadIdx.x;
    int chunk = (N + 1023) >> 10;
    int b = t * chunk, en = min(b + chunk, N);
    int sum = 0;
    for (int i = b; i < en; i++) sum += g_cursor[i];
    s_part[t] = sum;
    __syncthreads();
    for (int off = 1; off < 1024; off <<= 1) {
        int v = (t >= off) ? s_part[t - off] : 0;
        __syncthreads();
        s_part[t] += v;
        __syncthreads();
    }
    int run = s_part[t] - sum;   // exclusive base
    for (int i = b; i < en; i++) {
        int c = g_cursor[i];
        g_rowptr[i] = run;
        g_cursor[i] = run;
        run += c;
    }
    if (t == 0) g_rowptr[N] = E;
}
__global__ void scatter_kernel(const int* __restrict__ ei, int E) {
    int e = blockIdx.x * blockDim.x + threadIdx.x;
    if (e >= E) return;
    int src = ei[e], dst = ei[E + e];
    int pos = atomicAdd(&g_cursor[dst], 1);
    g_srcs[pos] = src;
}

// ---------------- x -> bf16 (bit-identical to GEMM's staging rounding) --------------
__global__ void cvt_x(const float* __restrict__ x, int total4) {
    int i = blockIdx.x * blockDim.x + threadIdx.x;   // over float4s
    if (i >= total4) return;
    float4 a = *(const float4*)&x[(size_t)i * 4];
    uint2 o;
    o.x = pack_bf16(a.x, a.y);
    o.y = pack_bf16(a.z, a.w);
    *(uint2*)&g_xb[(size_t)i * 4] = o;
}

// ---------------- pack B: weights -> packed bf16 k-pair image + bias -----------------
// g_Bph[(y*64 + kp)*64 + j] = bf16(W[2kp][y*64+j]) | bf16(W[2kp+1][y*64+j])<<16
// g_Bpl likewise for the residual of the skip block (y==12).
__global__ void pack_b(const float* __restrict__ Wq, const float* __restrict__ bq,
                       const float* __restrict__ Wk, const float* __restrict__ bk,
                       const float* __restrict__ Wv, const float* __restrict__ bv,
                       const float* __restrict__ Ws, const float* __restrict__ bs, int K) {
    int K2 = K >> 1;
    int idx = blockIdx.x * blockDim.x + threadIdx.x;
    int tot = OCT * K2;
    if (idx < tot) {
        int c  = idx / K2;          // global col 0..831
        int kp = idx - c * K2;      // k-pair
        const float* W; int cc; int ld;
        if      (c < 256) { W = Wq; cc = c;       ld = 256; }
        else if (c < 512) { W = Wk; cc = c - 256; ld = 256; }
        else if (c < 768) { W = Wv; cc = c - 512; ld = 256; }
        else              { W = Ws; cc = c - 768; ld = 64;  }
        float w0 = W[(2 * kp) * ld + cc];
        float w1 = W[(2 * kp + 1) * ld + cc];
        int y = c >> 6, j = c & 63;
        g_Bph[(y * 64 + kp) * 64 + j] = pack_bf16(w0, w1);
        if (y == 12)
            g_Bpl[kp * 64 + j] = pack_bf16(bf_hi_res(w0), bf_hi_res(w1));
    }
    if (idx < OCT) {
        float b;
        if      (idx < 256) b = bq[idx];
        else if (idx < 512) b = bk[idx - 256];
        else if (idx < 768) b = bv[idx - 512];
        else                b = bs[idx - 768];
        g_bc[idx] = b;
    }
}

// ---------------- GEMM: bf16 mma.sync.m16n8k16, A bf16, B pre-packed ----------------
// B-lo term only for the skip block (y==12).
#define ASTR32 136
#define BSTR32 72
__global__ void __launch_bounds__(256, 2) gemm_qkvs(const __nv_bfloat16* __restrict__ A,
                                                    int N, int K) {
    __shared__ uint32_t As[8 * ASTR32];      // [kpair][m]
    __shared__ uint32_t Bs[2][8 * BSTR32];   // [hi/lo][kpair][n]
    const int t    = threadIdx.x;
    const int lane = t & 31, wid = t >> 5;
    const int warp_m = wid & 3;
    const int warp_n = wid >> 2;
    const int row0 = blockIdx.x * 128, col0 = blockIdx.y * 64;
    const int lq = lane >> 2;
    const int lr = lane & 3;
    const bool need_lo = (blockIdx.y == 12);

    float c[2][4][4];
    #pragma unroll
    for (int mt = 0; mt < 2; mt++)
        #pragma unroll
        for (int nt = 0; nt < 4; nt++)
            #pragma unroll
            for (int i = 0; i < 4; i++) c[mt][nt][i] = 0.f;

    const uint32_t* Bsrc = &g_Bph[(size_t)blockIdx.y * 64 * 64];

    for (int k0 = 0; k0 < K; k0 += 16) {
        {   // A bf16 [N,K]: thread covers 8 elems (4 kpairs). 256 threads = 128 rows x 2 halves.
            int r = t >> 1, half = t & 1;
            int gr = row0 + r;
            uint4 a = (gr < N) ? *(const uint4*)&A[(size_t)gr * K + k0 + half * 8]
                               : make_uint4(0u, 0u, 0u, 0u);
            int kp = half * 4;
            As[(kp + 0) * ASTR32 + r] = a.x;
            As[(kp + 1) * ASTR32 + r] = a.y;
            As[(kp + 2) * ASTR32 + r] = a.z;
            As[(kp + 3) * ASTR32 + r] = a.w;
        }
        if (t < 128) {   // B: straight uint4 copies from pre-packed image
            int kp = t >> 4, j4 = (t & 15) << 2;
            int kbase = (k0 >> 1) + kp;
            uint4 bh4 = *(const uint4*)&Bsrc[kbase * 64 + j4];
            *(uint4*)&Bs[0][kp * BSTR32 + j4] = bh4;
            if (need_lo) {
                uint4 bl4 = *(const uint4*)&g_Bpl[kbase * 64 + j4];
                *(uint4*)&Bs[1][kp * BSTR32 + j4] = bl4;
            }
        }
        __syncthreads();

        uint32_t ah[2][4];
        #pragma unroll
        for (int mt = 0; mt < 2; mt++) {
            int r0 = warp_m * 32 + mt * 16 + lq;
            ah[mt][0] = As[lr * ASTR32 + r0];
            ah[mt][1] = As[lr * ASTR32 + r0 + 8];
            ah[mt][2] = As[(lr + 4) * ASTR32 + r0];
            ah[mt][3] = As[(lr + 4) * ASTR32 + r0 + 8];
        }
        uint32_t bh[4][2];
        #pragma unroll
        for (int nt = 0; nt < 4; nt++) {
            int n = warp_n * 32 + nt * 8 + lq;
            bh[nt][0] = Bs[0][lr * BSTR32 + n];
            bh[nt][1] = Bs[0][(lr + 4) * BSTR32 + n];
        }
        #pragma unroll
        for (int mt = 0; mt < 2; mt++)
            #pragma unroll
            for (int nt = 0; nt < 4; nt++)
                MMA_BF16(c[mt][nt], ah[mt], bh[nt]);
        if (need_lo) {
            uint32_t bl[4][2];
            #pragma unroll
            for (int nt = 0; nt < 4; nt++) {
                int n = warp_n * 32 + nt * 8 + lq;
                bl[nt][0] = Bs[1][lr * BSTR32 + n];
                bl[nt][1] = Bs[1][(lr + 4) * BSTR32 + n];
            }
            #pragma unroll
            for (int mt = 0; mt < 2; mt++)
                #pragma unroll
                for (int nt = 0; nt < 4; nt++)
                    MMA_BF16(c[mt][nt], ah[mt], bl[nt]);
        }
        __syncthreads();
    }

    int y = blockIdx.y;
    bool is_bf = (y < 12);
    __nv_bfloat16* bfdst; int bfoff;
    if      (y < 4) { bfdst = g_qb; bfoff = col0;       }
    else if (y < 8) { bfdst = g_kb; bfoff = col0 - 256; }
    else            { bfdst = g_vb; bfoff = col0 - 512; }

    #pragma unroll
    for (int mt = 0; mt < 2; mt++) {
        int r = row0 + warp_m * 32 + mt * 16 + lq;
        #pragma unroll
        for (int nt = 0; nt < 4; nt++) {
            int jc_in = warp_n * 32 + nt * 8 + lr * 2;
            float b0 = g_bc[col0 + jc_in];
            float b1 = g_bc[col0 + jc_in + 1];
            if (is_bf) {
                if (r < N) {
                    *(uint32_t*)&bfdst[(size_t)r * 256 + bfoff + jc_in] =
                        pack_bf16(c[mt][nt][0] + b0, c[mt][nt][1] + b1);
                }
                if (r + 8 < N) {
                    *(uint32_t*)&bfdst[(size_t)(r + 8) * 256 + bfoff + jc_in] =
                        pack_bf16(c[mt][nt][2] + b0, c[mt][nt][3] + b1);
                }
            } else {
                if (r < N) {
                    float2 o = make_float2(c[mt][nt][0] + b0, c[mt][nt][1] + b1);
                    *(float2*)&g_skip[(size_t)r * 64 + jc_in] = o;
                }
                if (r + 8 < N) {
                    float2 o = make_float2(c[mt][nt][2] + b0, c[mt][nt][3] + b1);
                    *(float2*)&g_skip[(size_t)(r + 8) * 64 + jc_in] = o;
                }
            }
        }
    }
}

// ---------------- fused edge conv: warp per dst node, 2-edge unrolled ----------------
template<int OUT_BF>
__global__ void __launch_bounds__(256, 4) fused_edge(void* __restrict__ outp, int N) {
    int node = (blockIdx.x * blockDim.x + threadIdx.x) >> 5;
    int lane = threadIdx.x & 31;
    if (node >= N) return;

    uint4 q = ((const uint4*)&g_qb[(size_t)node * QK])[lane];
    int beg = g_rowptr[node], end = g_rowptr[node + 1];

    float z = 0.f;
    float acc[8] = {0.f, 0.f, 0.f, 0.f, 0.f, 0.f, 0.f, 0.f};

    int i = beg;
    for (; i + 2 <= end; i += 2) {
        int s0 = g_srcs[i], s1 = g_srcs[i + 1];
        uint4 k0 = ((const uint4*)&g_kb[(size_t)s0 * QK])[lane];
        uint4 k1 = ((const uint4*)&g_kb[(size_t)s1 * QK])[lane];
        uint4 v0 = ((const uint4*)&g_vb[(size_t)s0 * QK])[lane];
        uint4 v1 = ((const uint4*)&g_vb[(size_t)s1 * QK])[lane];
        float p0 = dot2bf(q.x, k0.x) + dot2bf(q.y, k0.y) + dot2bf(q.z, k0.z) + dot2bf(q.w, k0.w);
        float p1 = dot2bf(q.x, k1.x) + dot2bf(q.y, k1.y) + dot2bf(q.z, k1.z) + dot2bf(q.w, k1.w);
        p0 += __shfl_xor_sync(0xffffffffu, p0, 1);
        p1 += __shfl_xor_sync(0xffffffffu, p1, 1);
        p0 += __shfl_xor_sync(0xffffffffu, p0, 2);
        p1 += __shfl_xor_sync(0xffffffffu, p1, 2);
        p0 += __shfl_xor_sync(0xffffffffu, p0, 4);
        p1 += __shfl_xor_sync(0xffffffffu, p1, 4);
        float e0 = __expf(p0 * 0.125f);
        float e1 = __expf(p1 * 0.125f);
        z += e0 + e1;
        const uint32_t* u0 = (const uint32_t*)&v0;
        const uint32_t* u1 = (const uint32_t*)&v1;
        #pragma unroll
        for (int j = 0; j < 4; j++) {
            acc[2 * j]     += e0 * bflo(u0[j]) + e1 * bflo(u1[j]);
            acc[2 * j + 1] += e0 * bfhi(u0[j]) + e1 * bfhi(u1[j]);
        }
    }
    if (i < end) {
        int s0 = g_srcs[i];
        uint4 k0 = ((const uint4*)&g_kb[(size_t)s0 * QK])[lane];
        uint4 v0 = ((const uint4*)&g_vb[(size_t)s0 * QK])[lane];
        float p0 = dot2bf(q.x, k0.x) + dot2bf(q.y, k0.y) + dot2bf(q.z, k0.z) + dot2bf(q.w, k0.w);
        p0 += __shfl_xor_sync(0xffffffffu, p0, 1);
        p0 += __shfl_xor_sync(0xffffffffu, p0, 2);
        p0 += __shfl_xor_sync(0xffffffffu, p0, 4);
        float e0 = __expf(p0 * 0.125f);
        z += e0;
        const uint32_t* u0 = (const uint32_t*)&v0;
        #pragma unroll
        for (int j = 0; j < 4; j++) {
            acc[2 * j]     += e0 * bflo(u0[j]);
            acc[2 * j + 1] += e0 * bfhi(u0[j]);
        }
    }

    float w = (end > beg) ? (0.25f / z) : 0.f;
    #pragma unroll
    for (int j = 0; j < 8; j++) {
        float a = acc[j] * w;
        a += __shfl_xor_sync(0xffffffffu, a, 8);
        a += __shfl_xor_sync(0xffffffffu, a, 16);
        acc[j] = a;
    }

    if (lane < 8) {
        const float* sp = &g_skip[(size_t)node * HID + lane * 8];
        float4 s0 = *(const float4*)sp;
        float4 s1 = *(const float4*)(sp + 4);
        float o[8];
        o[0] = fmaxf(acc[0] + s0.x, 0.f);
        o[1] = fmaxf(acc[1] + s0.y, 0.f);
        o[2] = fmaxf(acc[2] + s0.z, 0.f);
        o[3] = fmaxf(acc[3] + s0.w, 0.f);
        o[4] = fmaxf(acc[4] + s1.x, 0.f);
        o[5] = fmaxf(acc[5] + s1.y, 0.f);
        o[6] = fmaxf(acc[6] + s1.z, 0.f);
        o[7] = fmaxf(acc[7] + s1.w, 0.f);
        if (OUT_BF) {
            uint4 pb;
            pb.x = pack_bf16(o[0], o[1]);
            pb.y = pack_bf16(o[2], o[3]);
            pb.z = pack_bf16(o[4], o[5]);
            pb.w = pack_bf16(o[6], o[7]);
            *(uint4*)&((__nv_bfloat16*)outp)[(size_t)node * HID + lane * 8] = pb;
        } else {
            float* op = &((float*)outp)[(size_t)node * HID + lane * 8];
            *(float4*)op       = make_float4(o[0], o[1], o[2], o[3]);
            *(float4*)(op + 4) = make_float4(o[4], o[5], o[6], o[7]);
        }
    }
}

// ---------------- pool: per-graph mean of g_h2 (batch is sorted), 64 nodes/block ------
__global__ void pool_kernel(const int* __restrict__ batch, int N) {
    const int NPB = 64;
    int d = threadIdx.x;
    int n0 = blockIdx.x * NPB;
    int n1 = min(n0 + NPB, N);
    float acc = 0.f, cnt = 0.f;
    int cur = -1;
    for (int n = n0; n < n1; n++) {
        int g = batch[n];
        if (g != cur) {
            if (cur >= 0) {
                atomicAdd(&g_gsum[cur * HID + d], acc);
                if (d == 0) atomicAdd(&g_gcnt[cur], cnt);
            }
            cur = g; acc = 0.f; cnt = 0.f;
        }
        acc += g_h2[(size_t)n * HID + d];
        cnt += 1.f;
    }
    if (cur >= 0) {
        atomicAdd(&g_gsum[cur * HID + d], acc);
        if (d == 0) atomicAdd(&g_gcnt[cur], cnt);
    }
}

// ---------------- head: one block per graph ----------------
__global__ void __launch_bounds__(128, 8) head_kernel(
        const float* __restrict__ gf,
        const float* __restrict__ gW1, const float* __restrict__ gb1,
        const float* __restrict__ gW2, const float* __restrict__ gb2,
        const float* __restrict__ hW1, const float* __restrict__ hb1,
        const float* __restrict__ hW2, const float* __restrict__ hb2,
        float* __restrict__ out) {
    __shared__ float s_gf[GDIM];
    __shared__ float s_patch[HID];
    __shared__ float s_g1[HID];
    __shared__ float s_g2[HID];
    __shared__ float s_hid[HID];
    int g = blockIdx.x;
    int t = threadIdx.x;

    for (int i = t; i < GDIM; i += 128) s_gf[i] = gf[g * GDIM + i];
    if (t < HID) s_patch[t] = g_gsum[g * HID + t] / fmaxf(g_gcnt[g], 1.f);
    __syncthreads();

    {
        int j = t >> 1, half = t & 1;
        float s = 0.f;
        int kb = half * 128;
        #pragma unroll 8
        for (int k = 0; k < 128; k++) s += s_gf[kb + k] * gW1[(kb + k) * HID + j];
        s += __shfl_xor_sync(0xffffffffu, s, 1);
        if (half == 0) s_g1[j] = fmaxf(s + gb1[j], 0.f);
    }
    __syncthreads();

    if (t < HID) {
        float s = gb2[t];
        #pragma unroll 8
        for (int k = 0; k < HID; k++) s += s_g1[k] * gW2[k * HID + t];
        s_g2[t] = fmaxf(s, 0.f);
    }
    __syncthreads();

    {
        int j = t >> 1, half = t & 1;
        float s = 0.f;
        const float* src = half ? s_g2 : s_patch;
        int kb = half * HID;
        #pragma unroll 8
        for (int k = 0; k < HID; k++) s += src[k] * hW1[(kb + k) * HID + j];
        s += __shfl_xor_sync(0xffffffffu, s, 1);
        if (half == 0) s_hid[j] = fmaxf(s + hb1[j], 0.f);
    }
    __syncthreads();

    if (t < NCLS) {
        float s = hb2[t];
        #pragma unroll 8
        for (int k = 0; k < HID; k++) s += s_hid[k] * hW2[k * NCLS + t];
        out[g * NCLS + t] = s;
    }
}

// ---------------- host orchestration ----------------
extern "C" void kernel_launch(void* const* d_in, const int* in_sizes, int n_in,
                              void* d_out, int out_size) {
    const float* x     = (const float*)d_in[0];
    const int*   ei    = (const int*)  d_in[1];
    const int*   batch = (const int*)  d_in[2];
    const float* gf    = (const float*)d_in[3];
    const float* c1[8]; for (int i = 0; i < 8; i++) c1[i] = (const float*)d_in[4 + i];
    const float* c2[8]; for (int i = 0; i < 8; i++) c2[i] = (const float*)d_in[12 + i];
    const float* gW1 = (const float*)d_in[20]; const float* gb1 = (const float*)d_in[21];
    const float* gW2 = (const float*)d_in[22]; const float* gb2 = (const float*)d_in[23];
    const float* hW1 = (const float*)d_in[24]; const float* hb1 = (const float*)d_in[25];
    const float* hW2 = (const float*)d_in[26]; const float* hb2 = (const float*)d_in[27];

    int N = in_sizes[0] / 128;
    int E = in_sizes[1] / 2;

    void *p_xb, *p_h1b, *p_h2, *p_gsum, *p_gcnt, *p_cursor;
    cudaGetSymbolAddress(&p_xb,     g_xb);
    cudaGetSymbolAddress(&p_h1b,    g_h1b);
    cudaGetSymbolAddress(&p_h2,     g_h2);
    cudaGetSymbolAddress(&p_gsum,   g_gsum);
    cudaGetSymbolAddress(&p_gcnt,   g_gcnt);
    cudaGetSymbolAddress(&p_cursor, g_cursor);

    // ---- build CSR once (reused by both convs) ----
    cudaMemsetAsync(p_cursor, 0, (size_t)N * sizeof(int), 0);
    hist_kernel<<<(E + 255) / 256, 256>>>(ei, E);
    scan_kernel<<<1, 1024>>>(N, E);
    scatter_kernel<<<(E + 255) / 256, 256>>>(ei, E);

    // ---- x -> bf16 once (bit-identical to staging rounding) ----
    int total4 = N * 32;   // N*128 / 4
    cvt_x<<<(total4 + 255) / 256, 256>>>(x, total4);

    dim3 gg((N + 127) / 128, OCT / 64);

    // conv1 (in=128, bf16 A, bf16 out)
    pack_b<<<(OCT * 64 + 255) / 256, 256>>>(c1[0], c1[1], c1[2], c1[3],
                                            c1[4], c1[5], c1[6], c1[7], 128);
    gemm_qkvs<<<gg, 256>>>((const __nv_bfloat16*)p_xb, N, 128);
    fused_edge<1><<<(N * 32 + 255) / 256, 256>>>(p_h1b, N);

    // conv2 (in=64, bf16 A, fp32 out)
    pack_b<<<(OCT * 32 + 255) / 256, 256>>>(c2[0], c2[1], c2[2], c2[3],
                                            c2[4], c2[5], c2[6], c2[7], 64);
    gemm_qkvs<<<gg, 256>>>((const __nv_bfloat16*)p_h1b, N, 64);
    fused_edge<0><<<(N * 32 + 255) / 256, 256>>>(p_h2, N);

    // pooling
    cudaMemsetAsync(p_gsum, 0, NGRAPH * HID * sizeof(float), 0);
    cudaMemsetAsync(p_gcnt, 0, NGRAPH * sizeof(float), 0);
    pool_kernel<<<(N + 63) / 64, HID>>>(batch, N);

    // head (one block per graph)
    head_kernel<<<NGRAPH, 128>>>(gf, gW1, gb1, gW2, gb2, hW1, hb1, hW2, hb2, (float*)d_out);
}

// round 17
// speedup vs baseline: 1.2545x; 1.0882x over previous
#include <cuda_runtime.h>
#include <cuda_bf16.h>
#include <math.h>
#include <cstdint>

// Problem constants
#define NMAX   50000
#define EMAX   800000
#define HEADS  4
#define HID    64
#define QK     256        // HEADS*HID
#define OCT    832        // 3*QK + HID
#define NGRAPH 64
#define GDIM   256
#define NCLS   10

// ---------------- scratch (device globals; no runtime allocation) ----------------
__device__ __align__(16) __nv_bfloat16 g_qb[NMAX * QK];   // bf16 q
__device__ __align__(16) __nv_bfloat16 g_kb[NMAX * QK];   // bf16 k
__device__ __align__(16) __nv_bfloat16 g_vb[NMAX * QK];   // bf16 v
__device__ __align__(16) float    g_skip[NMAX * HID];
__device__ __align__(16) __nv_bfloat16 g_h1b[NMAX * HID]; // conv1 out (bf16 = GEMM2's A)
__device__ __align__(16) float    g_h2  [NMAX * HID];
__device__ __align__(16) uint32_t g_Bph[13 * 64 * 64];    // packed bf16 B (hi), [y][kp][n]
__device__ __align__(16) uint32_t g_Bpl[64 * 64];         // packed bf16 B (lo), skip block only
__device__ __align__(16) float    g_bc  [OCT];
__device__ __align__(16) float    g_gsum[NGRAPH * HID];
__device__ __align__(16) float    g_gcnt[NGRAPH];
// CSR (dst-sorted) graph, built once per launch
__device__ __align__(16) int      g_rowptr[NMAX + 1];
__device__ __align__(16) int      g_cursor[NMAX];
__device__ __align__(16) int      g_srcs  [EMAX];

// ---------------- helpers ----------------
__device__ __forceinline__ uint32_t pack_bf16(float a, float b) {
    __nv_bfloat16 ha = __float2bfloat16_rn(a);
    __nv_bfloat16 hb = __float2bfloat16_rn(b);
    return (uint32_t)__bfloat16_as_ushort(ha) | ((uint32_t)__bfloat16_as_ushort(hb) << 16);
}
__device__ __forceinline__ float bf_hi_res(float v) {   // v - bf16(v)
    return v - __bfloat162float(__float2bfloat16_rn(v));
}
__device__ __forceinline__ float bflo(uint32_t u) { return __uint_as_float(u << 16); }
__device__ __forceinline__ float bfhi(uint32_t u) { return __uint_as_float(u & 0xffff0000u); }
__device__ __forceinline__ float dot2bf(uint32_t ua, uint32_t ub) {
    return bflo(ua) * bflo(ub) + bfhi(ua) * bfhi(ub);
}

#define MMA_BF16(c, a, b)                                                     \
    asm volatile("mma.sync.aligned.m16n8k16.row.col.f32.bf16.bf16.f32 "       \
                 "{%0,%1,%2,%3}, {%4,%5,%6,%7}, {%8,%9}, {%0,%1,%2,%3};"      \
                 : "+f"((c)[0]), "+f"((c)[1]), "+f"((c)[2]), "+f"((c)[3])     \
                 : "r"((a)[0]), "r"((a)[1]), "r"((a)[2]), "r"((a)[3]),        \
                   "r"((b)[0]), "r"((b)[1]))

// ---------------- CSR build ----------------
__global__ void hist_kernel(const int* __restrict__ ei, int E) {
    int e = blockIdx.x * blockDim.x + threadIdx.x;
    if (e < E) atomicAdd(&g_cursor[ei[E + e]], 1);
}
__global__ void scan_kernel(int N, int E) {
    __shared__ int s_part[1024];
    int t = threadIdx.x;
    int chunk = (N + 1023) >> 10;
    int b = t * chunk, en = min(b + chunk, N);
    int sum = 0;
    for (int i = b; i < en; i++) sum += g_cursor[i];
    s_part[t] = sum;
    __syncthreads();
    for (int off = 1; off < 1024; off <<= 1) {
        int v = (t >= off) ? s_part[t - off] : 0;
        __syncthreads();
        s_part[t] += v;
        __syncthreads();
    }
    int run = s_part[t] - sum;   // exclusive base
    for (int i = b; i < en; i++) {
        int c = g_cursor[i];
        g_rowptr[i] = run;
        g_cursor[i] = run;
        run += c;
    }
    if (t == 0) g_rowptr[N] = E;
}
__global__ void scatter_kernel(const int* __restrict__ ei, int E) {
    int e = blockIdx.x * blockDim.x + threadIdx.x;
    if (e >= E) return;
    int src = ei[e], dst = ei[E + e];
    int pos = atomicAdd(&g_cursor[dst], 1);
    g_srcs[pos] = src;
}

// ---------------- pack B: weights -> packed bf16 k-pair image + bias -----------------
__global__ void pack_b(const float* __restrict__ Wq, const float* __restrict__ bq,
                       const float* __restrict__ Wk, const float* __restrict__ bk,
                       const float* __restrict__ Wv, const float* __restrict__ bv,
                       const float* __restrict__ Ws, const float* __restrict__ bs, int K) {
    int K2 = K >> 1;
    int idx = blockIdx.x * blockDim.x + threadIdx.x;
    int tot = OCT * K2;
    if (idx < tot) {
        int c  = idx / K2;          // global col 0..831
        int kp = idx - c * K2;      // k-pair
        const float* W; int cc; int ld;
        if      (c < 256) { W = Wq; cc = c;       ld = 256; }
        else if (c < 512) { W = Wk; cc = c - 256; ld = 256; }
        else if (c < 768) { W = Wv; cc = c - 512; ld = 256; }
        else              { W = Ws; cc = c - 768; ld = 64;  }
        float w0 = W[(2 * kp) * ld + cc];
        float w1 = W[(2 * kp + 1) * ld + cc];
        int y = c >> 6, j = c & 63;
        g_Bph[(y * 64 + kp) * 64 + j] = pack_bf16(w0, w1);
        if (y == 12)
            g_Bpl[kp * 64 + j] = pack_bf16(bf_hi_res(w0), bf_hi_res(w1));
    }
    if (idx < OCT) {
        float b;
        if      (idx < 256) b = bq[idx];
        else if (idx < 512) b = bk[idx - 256];
        else if (idx < 768) b = bv[idx - 512];
        else                b = bs[idx - 768];
        g_bc[idx] = b;
    }
}

// ---------------- GEMM: A-resident bf16 mma.sync.m16n8k16 ---------------------------
// One CTA per 128-row slab: A staged to smem ONCE (packed bf16 k-pairs), then loop
// over all 13 column blocks. B-lo term only for the skip block (y==12).
#define ASTR32 136
#define BSTR32 72
template<int IN_BF>
__global__ void __launch_bounds__(256, 2) gemm_qkvs(const void* __restrict__ Ap, int N, int K) {
    __shared__ uint32_t As[64 * ASTR32];     // [kpair][m], up to K=128
    __shared__ uint32_t Bs[2][8 * BSTR32];   // [hi/lo][kpair][n]
    const int t    = threadIdx.x;
    const int lane = t & 31, wid = t >> 5;
    const int warp_m = wid & 3;
    const int warp_n = wid >> 2;
    const int row0 = blockIdx.x * 128;
    const int lq = lane >> 2;
    const int lr = lane & 3;
    const int K2 = K >> 1;

    // ---- stage A once ----
    if (IN_BF) {
        const __nv_bfloat16* A = (const __nv_bfloat16*)Ap;
        int nu4 = 128 * (K >> 3);            // uint4 count
        for (int idx = t; idx < nu4; idx += 256) {
            int r = idx / (K >> 3), h = idx - r * (K >> 3);
            int gr = row0 + r;
            uint4 a = (gr < N) ? *(const uint4*)&A[(size_t)gr * K + h * 8]
                               : make_uint4(0u, 0u, 0u, 0u);
            int kp = h * 4;
            As[(kp + 0) * ASTR32 + r] = a.x;
            As[(kp + 1) * ASTR32 + r] = a.y;
            As[(kp + 2) * ASTR32 + r] = a.z;
            As[(kp + 3) * ASTR32 + r] = a.w;
        }
    } else {
        const float* A = (const float*)Ap;
        int nf4 = 128 * (K >> 2);            // float4 count
        for (int idx = t; idx < nf4; idx += 256) {
            int r = idx / (K >> 2), h = idx - r * (K >> 2);
            int gr = row0 + r;
            float4 a = (gr < N) ? *(const float4*)&A[(size_t)gr * K + h * 4]
                                : make_float4(0.f, 0.f, 0.f, 0.f);
            int kp = h * 2;
            As[(kp + 0) * ASTR32 + r] = pack_bf16(a.x, a.y);
            As[(kp + 1) * ASTR32 + r] = pack_bf16(a.z, a.w);
        }
    }
    __syncthreads();

    // ---- loop over 13 column blocks ----
    for (int y = 0; y < 13; y++) {
        const bool need_lo = (y == 12);
        const int col0 = y * 64;
        const uint32_t* Bsrc = &g_Bph[(size_t)y * 64 * 64];

        float c[2][4][4];
        #pragma unroll
        for (int mt = 0; mt < 2; mt++)
            #pragma unroll
            for (int nt = 0; nt < 4; nt++)
                #pragma unroll
                for (int i = 0; i < 4; i++) c[mt][nt][i] = 0.f;

        for (int k0 = 0; k0 < K; k0 += 16) {
            if (t < 128) {   // stage B: straight uint4 copies from pre-packed image
                int kp = t >> 4, j4 = (t & 15) << 2;
                int kbase = (k0 >> 1) + kp;
                *(uint4*)&Bs[0][kp * BSTR32 + j4] = *(const uint4*)&Bsrc[kbase * 64 + j4];
                if (need_lo)
                    *(uint4*)&Bs[1][kp * BSTR32 + j4] = *(const uint4*)&g_Bpl[kbase * 64 + j4];
            }
            __syncthreads();

            int kb = k0 >> 1;
            uint32_t ah[2][4];
            #pragma unroll
            for (int mt = 0; mt < 2; mt++) {
                int r0 = warp_m * 32 + mt * 16 + lq;
                ah[mt][0] = As[(kb + lr) * ASTR32 + r0];
                ah[mt][1] = As[(kb + lr) * ASTR32 + r0 + 8];
                ah[mt][2] = As[(kb + lr + 4) * ASTR32 + r0];
                ah[mt][3] = As[(kb + lr + 4) * ASTR32 + r0 + 8];
            }
            uint32_t bh[4][2];
            #pragma unroll
            for (int nt = 0; nt < 4; nt++) {
                int n = warp_n * 32 + nt * 8 + lq;
                bh[nt][0] = Bs[0][lr * BSTR32 + n];
                bh[nt][1] = Bs[0][(lr + 4) * BSTR32 + n];
            }
            #pragma unroll
            for (int mt = 0; mt < 2; mt++)
                #pragma unroll
                for (int nt = 0; nt < 4; nt++)
                    MMA_BF16(c[mt][nt], ah[mt], bh[nt]);
            if (need_lo) {
                uint32_t bl[4][2];
                #pragma unroll
                for (int nt = 0; nt < 4; nt++) {
                    int n = warp_n * 32 + nt * 8 + lq;
                    bl[nt][0] = Bs[1][lr * BSTR32 + n];
                    bl[nt][1] = Bs[1][(lr + 4) * BSTR32 + n];
                }
                #pragma unroll
                for (int mt = 0; mt < 2; mt++)
                    #pragma unroll
                    for (int nt = 0; nt < 4; nt++)
                        MMA_BF16(c[mt][nt], ah[mt], bl[nt]);
            }
            __syncthreads();
        }

        // ---- epilogue for this column block ----
        bool is_bf = (y < 12);
        __nv_bfloat16* bfdst; int bfoff;
        if      (y < 4) { bfdst = g_qb; bfoff = col0;       }
        else if (y < 8) { bfdst = g_kb; bfoff = col0 - 256; }
        else            { bfdst = g_vb; bfoff = col0 - 512; }

        #pragma unroll
        for (int mt = 0; mt < 2; mt++) {
            int r = row0 + warp_m * 32 + mt * 16 + lq;
            #pragma unroll
            for (int nt = 0; nt < 4; nt++) {
                int jc_in = warp_n * 32 + nt * 8 + lr * 2;
                float b0 = g_bc[col0 + jc_in];
                float b1 = g_bc[col0 + jc_in + 1];
                if (is_bf) {
                    if (r < N) {
                        *(uint32_t*)&bfdst[(size_t)r * 256 + bfoff + jc_in] =
                            pack_bf16(c[mt][nt][0] + b0, c[mt][nt][1] + b1);
                    }
                    if (r + 8 < N) {
                        *(uint32_t*)&bfdst[(size_t)(r + 8) * 256 + bfoff + jc_in] =
                            pack_bf16(c[mt][nt][2] + b0, c[mt][nt][3] + b1);
                    }
                } else {
                    if (r < N) {
                        float2 o = make_float2(c[mt][nt][0] + b0, c[mt][nt][1] + b1);
                        *(float2*)&g_skip[(size_t)r * 64 + jc_in] = o;
                    }
                    if (r + 8 < N) {
                        float2 o = make_float2(c[mt][nt][2] + b0, c[mt][nt][3] + b1);
                        *(float2*)&g_skip[(size_t)(r + 8) * 64 + jc_in] = o;
                    }
                }
            }
        }
    }
}

// ---------------- fused edge conv: warp per dst node, 2-edge unrolled ----------------
template<int OUT_BF>
__global__ void __launch_bounds__(256, 4) fused_edge(void* __restrict__ outp, int N) {
    int node = (blockIdx.x * blockDim.x + threadIdx.x) >> 5;
    int lane = threadIdx.x & 31;
    if (node >= N) return;

    uint4 q = ((const uint4*)&g_qb[(size_t)node * QK])[lane];
    int beg = g_rowptr[node], end = g_rowptr[node + 1];

    float z = 0.f;
    float acc[8] = {0.f, 0.f, 0.f, 0.f, 0.f, 0.f, 0.f, 0.f};

    int i = beg;
    for (; i + 2 <= end; i += 2) {
        int s0 = g_srcs[i], s1 = g_srcs[i + 1];
        uint4 k0 = ((const uint4*)&g_kb[(size_t)s0 * QK])[lane];
        uint4 k1 = ((const uint4*)&g_kb[(size_t)s1 * QK])[lane];
        uint4 v0 = ((const uint4*)&g_vb[(size_t)s0 * QK])[lane];
        uint4 v1 = ((const uint4*)&g_vb[(size_t)s1 * QK])[lane];
        float p0 = dot2bf(q.x, k0.x) + dot2bf(q.y, k0.y) + dot2bf(q.z, k0.z) + dot2bf(q.w, k0.w);
        float p1 = dot2bf(q.x, k1.x) + dot2bf(q.y, k1.y) + dot2bf(q.z, k1.z) + dot2bf(q.w, k1.w);
        p0 += __shfl_xor_sync(0xffffffffu, p0, 1);
        p1 += __shfl_xor_sync(0xffffffffu, p1, 1);
        p0 += __shfl_xor_sync(0xffffffffu, p0, 2);
        p1 += __shfl_xor_sync(0xffffffffu, p1, 2);
        p0 += __shfl_xor_sync(0xffffffffu, p0, 4);
        p1 += __shfl_xor_sync(0xffffffffu, p1, 4);
        float e0 = __expf(p0 * 0.125f);
        float e1 = __expf(p1 * 0.125f);
        z += e0 + e1;
        const uint32_t* u0 = (const uint32_t*)&v0;
        const uint32_t* u1 = (const uint32_t*)&v1;
        #pragma unroll
        for (int j = 0; j < 4; j++) {
            acc[2 * j]     += e0 * bflo(u0[j]) + e1 * bflo(u1[j]);
            acc[2 * j + 1] += e0 * bfhi(u0[j]) + e1 * bfhi(u1[j]);
        }
    }
    if (i < end) {
        int s0 = g_srcs[i];
        uint4 k0 = ((const uint4*)&g_kb[(size_t)s0 * QK])[lane];
        uint4 v0 = ((const uint4*)&g_vb[(size_t)s0 * QK])[lane];
        float p0 = dot2bf(q.x, k0.x) + dot2bf(q.y, k0.y) + dot2bf(q.z, k0.z) + dot2bf(q.w, k0.w);
        p0 += __shfl_xor_sync(0xffffffffu, p0, 1);
        p0 += __shfl_xor_sync(0xffffffffu, p0, 2);
        p0 += __shfl_xor_sync(0xffffffffu, p0, 4);
        float e0 = __expf(p0 * 0.125f);
        z += e0;
        const uint32_t* u0 = (const uint32_t*)&v0;
        #pragma unroll
        for (int j = 0; j < 4; j++) {
            acc[2 * j]     += e0 * bflo(u0[j]);
            acc[2 * j + 1] += e0 * bfhi(u0[j]);
        }
    }

    float w = (end > beg) ? (0.25f / z) : 0.f;
    #pragma unroll
    for (int j = 0; j < 8; j++) {
        float a = acc[j] * w;
        a += __shfl_xor_sync(0xffffffffu, a, 8);
        a += __shfl_xor_sync(0xffffffffu, a, 16);
        acc[j] = a;
    }

    if (lane < 8) {
        const float* sp = &g_skip[(size_t)node * HID + lane * 8];
        float4 s0 = *(const float4*)sp;
        float4 s1 = *(const float4*)(sp + 4);
        float o[8];
        o[0] = fmaxf(acc[0] + s0.x, 0.f);
        o[1] = fmaxf(acc[1] + s0.y, 0.f);
        o[2] = fmaxf(acc[2] + s0.z, 0.f);
        o[3] = fmaxf(acc[3] + s0.w, 0.f);
        o[4] = fmaxf(acc[4] + s1.x, 0.f);
        o[5] = fmaxf(acc[5] + s1.y, 0.f);
        o[6] = fmaxf(acc[6] + s1.z, 0.f);
        o[7] = fmaxf(acc[7] + s1.w, 0.f);
        if (OUT_BF) {
            uint4 pb;
            pb.x = pack_bf16(o[0], o[1]);
            pb.y = pack_bf16(o[2], o[3]);
            pb.z = pack_bf16(o[4], o[5]);
            pb.w = pack_bf16(o[6], o[7]);
            *(uint4*)&((__nv_bfloat16*)outp)[(size_t)node * HID + lane * 8] = pb;
        } else {
            float* op = &((float*)outp)[(size_t)node * HID + lane * 8];
            *(float4*)op       = make_float4(o[0], o[1], o[2], o[3]);
            *(float4*)(op + 4) = make_float4(o[4], o[5], o[6], o[7]);
        }
    }
}

// ---------------- pool: per-graph mean of g_h2 (batch is sorted), 64 nodes/block ------
__global__ void pool_kernel(const int* __restrict__ batch, int N) {
    const int NPB = 64;
    int d = threadIdx.x;
    int n0 = blockIdx.x * NPB;
    int n1 = min(n0 + NPB, N);
    float acc = 0.f, cnt = 0.f;
    int cur = -1;
    for (int n = n0; n < n1; n++) {
        int g = batch[n];
        if (g != cur) {
            if (cur >= 0) {
                atomicAdd(&g_gsum[cur * HID + d], acc);
                if (d == 0) atomicAdd(&g_gcnt[cur], cnt);
            }
            cur = g; acc = 0.f; cnt = 0.f;
        }
        acc += g_h2[(size_t)n * HID + d];
        cnt += 1.f;
    }
    if (cur >= 0) {
        atomicAdd(&g_gsum[cur * HID + d], acc);
        if (d == 0) atomicAdd(&g_gcnt[cur], cnt);
    }
}

// ---------------- head: one block per graph ----------------
__global__ void __launch_bounds__(128, 8) head_kernel(
        const float* __restrict__ gf,
        const float* __restrict__ gW1, const float* __restrict__ gb1,
        const float* __restrict__ gW2, const float* __restrict__ gb2,
        const float* __restrict__ hW1, const float* __restrict__ hb1,
        const float* __restrict__ hW2, const float* __restrict__ hb2,
        float* __restrict__ out) {
    __shared__ float s_gf[GDIM];
    __shared__ float s_patch[HID];
    __shared__ float s_g1[HID];
    __shared__ float s_g2[HID];
    __shared__ float s_hid[HID];
    int g = blockIdx.x;
    int t = threadIdx.x;

    for (int i = t; i < GDIM; i += 128) s_gf[i] = gf[g * GDIM + i];
    if (t < HID) s_patch[t] = g_gsum[g * HID + t] / fmaxf(g_gcnt[g], 1.f);
    __syncthreads();

    {
        int j = t >> 1, half = t & 1;
        float s = 0.f;
        int kb = half * 128;
        #pragma unroll 8
        for (int k = 0; k < 128; k++) s += s_gf[kb + k] * gW1[(kb + k) * HID + j];
        s += __shfl_xor_sync(0xffffffffu, s, 1);
        if (half == 0) s_g1[j] = fmaxf(s + gb1[j], 0.f);
    }
    __syncthreads();

    if (t < HID) {
        float s = gb2[t];
        #pragma unroll 8
        for (int k = 0; k < HID; k++) s += s_g1[k] * gW2[k * HID + t];
        s_g2[t] = fmaxf(s, 0.f);
    }
    __syncthreads();

    {
        int j = t >> 1, half = t & 1;
        float s = 0.f;
        const float* src = half ? s_g2 : s_patch;
        int kb = half * HID;
        #pragma unroll 8
        for (int k = 0; k < HID; k++) s += src[k] * hW1[(kb + k) * HID + j];
        s += __shfl_xor_sync(0xffffffffu, s, 1);
        if (half == 0) s_hid[j] = fmaxf(s + hb1[j], 0.f);
    }
    __syncthreads();

    if (t < NCLS) {
        float s = hb2[t];
        #pragma unroll 8
        for (int k = 0; k < HID; k++) s += s_hid[k] * hW2[k * NCLS + t];
        out[g * NCLS + t] = s;
    }
}

// ---------------- host orchestration ----------------
extern "C" void kernel_launch(void* const* d_in, const int* in_sizes, int n_in,
                              void* d_out, int out_size) {
    const float* x     = (const float*)d_in[0];
    const int*   ei    = (const int*)  d_in[1];
    const int*   batch = (const int*)  d_in[2];
    const float* gf    = (const float*)d_in[3];
    const float* c1[8]; for (int i = 0; i < 8; i++) c1[i] = (const float*)d_in[4 + i];
    const float* c2[8]; for (int i = 0; i < 8; i++) c2[i] = (const float*)d_in[12 + i];
    const float* gW1 = (const float*)d_in[20]; const float* gb1 = (const float*)d_in[21];
    const float* gW2 = (const float*)d_in[22]; const float* gb2 = (const float*)d_in[23];
    const float* hW1 = (const float*)d_in[24]; const float* hb1 = (const float*)d_in[25];
    const float* hW2 = (const float*)d_in[26]; const float* hb2 = (const float*)d_in[27];

    int N = in_sizes[0] / 128;
    int E = in_sizes[1] / 2;

    void *p_h1b, *p_h2, *p_gsum, *p_gcnt, *p_cursor;
    cudaGetSymbolAddress(&p_h1b,    g_h1b);
    cudaGetSymbolAddress(&p_h2,     g_h2);
    cudaGetSymbolAddress(&p_gsum,   g_gsum);
    cudaGetSymbolAddress(&p_gcnt,   g_gcnt);
    cudaGetSymbolAddress(&p_cursor, g_cursor);

    // ---- build CSR once (reused by both convs) ----
    cudaMemsetAsync(p_cursor, 0, (size_t)N * sizeof(int), 0);
    hist_kernel<<<(E + 255) / 256, 256>>>(ei, E);
    scan_kernel<<<1, 1024>>>(N, E);
    scatter_kernel<<<(E + 255) / 256, 256>>>(ei, E);

    int gemm_grid = (N + 127) / 128;

    // conv1 (in=128, fp32 A read once, bf16 out)
    pack_b<<<(OCT * 64 + 255) / 256, 256>>>(c1[0], c1[1], c1[2], c1[3],
                                            c1[4], c1[5], c1[6], c1[7], 128);
    gemm_qkvs<0><<<gemm_grid, 256>>>(x, N, 128);
    fused_edge<1><<<(N * 32 + 255) / 256, 256>>>(p_h1b, N);

    // conv2 (in=64, bf16 A, fp32 out)
    pack_b<<<(OCT * 32 + 255) / 256, 256>>>(c2[0], c2[1], c2[2], c2[3],
                                            c2[4], c2[5], c2[6], c2[7], 64);
    gemm_qkvs<1><<<gemm_grid, 256>>>(p_h1b, N, 64);
    fused_edge<0><<<(N * 32 + 255) / 256, 256>>>(p_h2, N);

    // pooling
    cudaMemsetAsync(p_gsum, 0, NGRAPH * HID * sizeof(float), 0);
    cudaMemsetAsync(p_gcnt, 0, NGRAPH * sizeof(float), 0);
    pool_kernel<<<(N + 63) / 64, HID>>>(batch, N);

    // head (one block per graph)
    head_kernel<<<NGRAPH, 128>>>(gf, gW1, gb1, gW2, gb2, hW1, hb1, hW2, hb2, (float*)d_out);
}